// round 14
// baseline (speedup 1.0000x reference)
#include <cuda_runtime.h>
#include <cuda_fp16.h>
#include <cstdint>

// Problem constants
#define BDIM  4096
#define TDIM  32
#define KDIM  16
#define DDIM  512
#define HDIM  1024   // = 2*D
#define H2DIM 2048   // = 2*H

// NOTE: harness PTX target is compute_103 (no 'a') -> tcgen05/TMEM rejected.
// Legacy mma.sync HMMA is the tensor path. All GEMMs single-pass fp16.
// R14 experiment: 3 CTAs/SM (24 warps) via warp tile 32x32 / BN=64 / ~80 regs.
// Pipeline schedule identical to R10 (3-stage, wait_group 1, per-n-tile).

// ---------------------------------------------------------------------------
// Scratch (device globals: allocation-free rule)
// ---------------------------------------------------------------------------
__device__ float E1_buf[BDIM * HDIM];
__device__ float E2_buf[BDIM * H2DIM];
__device__ float e_buf[BDIM * TDIM];

__device__ __half Xh_buf[BDIM * TDIM * DDIM];
__device__ __half Gh_buf[BDIM * KDIM * DDIM];
__device__ __half W1h_buf[2 * DDIM * HDIM];   // full W1 (1024 x 1024)
__device__ __half M1h_buf[2 * DDIM * H2DIM];  // full M1 (1024 x 2048)
__device__ __half ghh_buf[BDIM * DDIM];
__device__ __half xhh_buf[BDIM * DDIM];

// ---------------------------------------------------------------------------
// PTX helpers
// ---------------------------------------------------------------------------
__device__ __forceinline__ void cp16(uint32_t dst, const void* src) {
    asm volatile("cp.async.cg.shared.global [%0], [%1], 16;\n"
                 :: "r"(dst), "l"(src) : "memory");
}
__device__ __forceinline__ void cp_commit() {
    asm volatile("cp.async.commit_group;\n" ::: "memory");
}
__device__ __forceinline__ void cp_wait1() {
    asm volatile("cp.async.wait_group 1;\n" ::: "memory");
}
__device__ __forceinline__ void ldsm_x4(unsigned& d0, unsigned& d1, unsigned& d2,
                                        unsigned& d3, uint32_t addr) {
    asm volatile("ldmatrix.sync.aligned.m8n8.x4.shared.b16 {%0,%1,%2,%3}, [%4];\n"
                 : "=r"(d0), "=r"(d1), "=r"(d2), "=r"(d3) : "r"(addr));
}
__device__ __forceinline__ void ldsm_x4_t(unsigned& d0, unsigned& d1, unsigned& d2,
                                          unsigned& d3, uint32_t addr) {
    asm volatile("ldmatrix.sync.aligned.m8n8.x4.trans.shared.b16 {%0,%1,%2,%3}, [%4];\n"
                 : "=r"(d0), "=r"(d1), "=r"(d2), "=r"(d3) : "r"(addr));
}
__device__ __forceinline__ void mma16816(float c[4], const unsigned a[4], const unsigned b[2]) {
    asm volatile(
        "mma.sync.aligned.m16n8k16.row.col.f32.f16.f16.f32 "
        "{%0,%1,%2,%3}, {%4,%5,%6,%7}, {%8,%9}, {%0,%1,%2,%3};\n"
        : "+f"(c[0]), "+f"(c[1]), "+f"(c[2]), "+f"(c[3])
        : "r"(a[0]), "r"(a[1]), "r"(a[2]), "r"(a[3]), "r"(b[0]), "r"(b[1]));
}

// ---------------------------------------------------------------------------
// convert-only: hi = fp16(x)
// ---------------------------------------------------------------------------
__global__ void conv_fp16_kernel(const float* __restrict__ src,
                                 __half* __restrict__ hi)
{
    int i = blockIdx.x * blockDim.x + threadIdx.x;
    float4 v = ((const float4*)src)[i];
    __half h[4];
    h[0] = __float2half_rn(v.x); h[1] = __float2half_rn(v.y);
    h[2] = __float2half_rn(v.z); h[3] = __float2half_rn(v.w);
    ((uint2*)hi)[i] = *(uint2*)h;
}

// ---------------------------------------------------------------------------
// fused: G -> Gh (fp16) AND ghh = fp16(mean_k G)   (single read of G)
// ---------------------------------------------------------------------------
__global__ void gconv_gmean_kernel(const float* __restrict__ G,
                                   __half* __restrict__ Gh,
                                   __half* __restrict__ ghh)
{
    int idx = blockIdx.x * blockDim.x + threadIdx.x;   // over B * (D/4)
    int b  = idx >> 7;
    int ch = idx & 127;
    const float4* gp = (const float4*)(G + (size_t)b * KDIM * DDIM + ch * 4);
    float4 acc = make_float4(0.f, 0.f, 0.f, 0.f);
#pragma unroll
    for (int k = 0; k < KDIM; k++) {
        float4 v = gp[k * (DDIM / 4)];
        __half h[4];
        h[0] = __float2half_rn(v.x); h[1] = __float2half_rn(v.y);
        h[2] = __float2half_rn(v.z); h[3] = __float2half_rn(v.w);
        ((uint2*)Gh)[((size_t)b * KDIM * DDIM + (size_t)k * DDIM) / 4 + ch] = *(uint2*)h;
        acc.x += v.x; acc.y += v.y; acc.z += v.z; acc.w += v.w;
    }
    const float inv = 1.0f / KDIM;
    __half m[4];
    m[0] = __float2half_rn(acc.x * inv); m[1] = __float2half_rn(acc.y * inv);
    m[2] = __float2half_rn(acc.z * inv); m[3] = __float2half_rn(acc.w * inv);
    ((uint2*)ghh)[idx] = *(uint2*)m;
}

// ---------------------------------------------------------------------------
// fp16 tensor-core GEMM. BM=128, BN=64, BK=32, 8 warps (4m x 2n),
// warp tile 32x32 (32 accum regs). 3-stage cp.async pipeline per n-tile
// (R10 schedule). 3 CTAs/SM.
// REDUCE=true : out[row] = sum_n relu(acc + Eb[row>>RPB_SHIFT, n]) * wvec[n] (+sc)
//               grid = (M/128), loops all N/64 tiles internally.
// REDUCE=false: out[row,col] = acc + bias[col]; grid = (M/128, N/64).
// ---------------------------------------------------------------------------
constexpr int ASZ = 128 * 40 * 2;     // A stage: 128 rows x 40-half stride
constexpr int BSZ = 32 * 72 * 2;      // B stage: 32 k-rows x 72-half stride
constexpr int NSTG = 3;
constexpr int SMEM_BYTES = NSTG * (ASZ + BSZ) + 128 * 2 * 4;
constexpr int NKT = DDIM / 32;        // 16 k-tiles

template <int RPB_SHIFT, bool REDUCE>
__global__ void __launch_bounds__(256, 3) mma_gemm(
    const __half* __restrict__ Ah,
    const __half* __restrict__ Bh,
    const float* __restrict__ EbOrBias,
    const float* __restrict__ wvec,
    const float* __restrict__ addsc,
    float* __restrict__ out,
    int N)
{
    extern __shared__ __align__(16) char smraw[];
    float* red = (float*)(smraw + NSTG * (ASZ + BSZ));   // [128][2]

    const int tid  = threadIdx.x;
    const int lane = tid & 31;
    const int wid  = tid >> 5;
    const int warp_m = wid & 3;       // 4 warps in M
    const int warp_n = wid >> 2;      // 2 warps in N
    const int lq = lane >> 2, lr = lane & 3;
    const int rb = blockIdx.x * 128;

    const uint32_t uS = (uint32_t)__cvta_generic_to_shared(smraw);
    const uint32_t uA = uS;
    const uint32_t uB = uS + NSTG * ASZ;

    // staging chunk coords: A 2 chunks/thread (128x32 halves), B 1 chunk (32x64)
    int am[2], ak[2];
#pragma unroll
    for (int c = 0; c < 2; c++) {
        int cid = tid + c * 256;
        am[c] = cid >> 2;  ak[c] = (cid & 3) << 3;
    }
    const int bk0 = tid >> 3;
    const int bn0 = (tid & 7) << 3;

    // ldmatrix per-lane address components
    const uint32_t a_frag_off =
        (uint32_t)(((warp_m * 32 + (lane & 15)) * 40 + ((lane & 16) >> 1)) * 2);
    const uint32_t b_frag_off =
        (uint32_t)(((lane & 15) * 72 + warp_n * 32 + ((lane & 16) >> 1)) * 2);

    float rs[2][2] = {{0.f, 0.f}, {0.f, 0.f}};
    const int ntiles = REDUCE ? (N >> 6) : 1;

    for (int nt = 0; nt < ntiles; nt++) {
        const int cb = REDUCE ? (nt << 6) : ((int)blockIdx.y << 6);

        float c[2][4][4] = {};

        auto stage = [&](int buf, int kt) {
            const int koff = kt << 5;
            const uint32_t adst0 = uA + (uint32_t)(buf * ASZ);
            const uint32_t bdst0 = uB + (uint32_t)(buf * BSZ);
#pragma unroll
            for (int cc = 0; cc < 2; cc++) {
                cp16(adst0 + (uint32_t)((am[cc] * 40 + ak[cc]) * 2),
                     Ah + (size_t)(rb + am[cc]) * DDIM + koff + ak[cc]);
            }
            cp16(bdst0 + (uint32_t)((bk0 * 72 + bn0) * 2),
                 Bh + (size_t)(koff + bk0) * N + cb + bn0);
        };

        stage(0, 0);
        cp_commit();

        for (int kt = 0; kt < NKT; kt++) {
            if (kt < NKT - 1) stage((kt + 1) % NSTG, kt + 1);
            cp_commit();
            cp_wait1();
            __syncthreads();

            const int buf = kt % NSTG;
            const uint32_t Ahb = uA + (uint32_t)(buf * ASZ) + a_frag_off;
            const uint32_t Bhb = uB + (uint32_t)(buf * BSZ) + b_frag_off;

#pragma unroll
            for (int kk = 0; kk < 32; kk += 16) {
                unsigned ah[2][4], bh[4][2];
#pragma unroll
                for (int mi = 0; mi < 2; mi++)
                    ldsm_x4(ah[mi][0], ah[mi][1], ah[mi][2], ah[mi][3],
                            Ahb + (uint32_t)((mi * 16 * 40 + kk) * 2));
#pragma unroll
                for (int gg = 0; gg < 2; gg++)
                    ldsm_x4_t(bh[2*gg][0], bh[2*gg][1], bh[2*gg+1][0], bh[2*gg+1][1],
                              Bhb + (uint32_t)((kk * 72 + gg * 16) * 2));
#pragma unroll
                for (int mi = 0; mi < 2; mi++)
#pragma unroll
                    for (int ni = 0; ni < 4; ni++)
                        mma16816(c[mi][ni], ah[mi], bh[ni]);
            }
            __syncthreads();
        }

        if (REDUCE) {
            // fused epilogue: relu(acc + Eb) . wvec
#pragma unroll
            for (int mi = 0; mi < 2; mi++) {
                int row0 = rb + warp_m * 32 + mi * 16 + lq;
                int row1 = row0 + 8;
                const float* Eb0 = EbOrBias + (size_t)(row0 >> RPB_SHIFT) * N;
                const float* Eb1 = EbOrBias + (size_t)(row1 >> RPB_SHIFT) * N;
#pragma unroll
                for (int ni = 0; ni < 4; ni++) {
                    int col = cb + warp_n * 32 + ni * 8 + lr * 2;
                    float2 e0 = *(const float2*)&Eb0[col];
                    float2 e1 = *(const float2*)&Eb1[col];
                    float2 wv = *(const float2*)&wvec[col];
                    rs[mi][0] += fmaxf(c[mi][ni][0] + e0.x, 0.f) * wv.x
                               + fmaxf(c[mi][ni][1] + e0.y, 0.f) * wv.y;
                    rs[mi][1] += fmaxf(c[mi][ni][2] + e1.x, 0.f) * wv.x
                               + fmaxf(c[mi][ni][3] + e1.y, 0.f) * wv.y;
                }
            }
        } else {
            // plain store epilogue: C = acc + bias
#pragma unroll
            for (int mi = 0; mi < 2; mi++) {
                int row0 = rb + warp_m * 32 + mi * 16 + lq;
                int row1 = row0 + 8;
#pragma unroll
                for (int ni = 0; ni < 4; ni++) {
                    int col = cb + warp_n * 32 + ni * 8 + lr * 2;
                    float2 bv = *(const float2*)&EbOrBias[col];
                    float2 o0, o1;
                    o0.x = c[mi][ni][0] + bv.x; o0.y = c[mi][ni][1] + bv.y;
                    o1.x = c[mi][ni][2] + bv.x; o1.y = c[mi][ni][3] + bv.y;
                    *(float2*)&out[(size_t)row0 * N + col] = o0;
                    *(float2*)&out[(size_t)row1 * N + col] = o1;
                }
            }
        }
    }

    if (REDUCE) {
        // reduce across the 4 lanes sharing each row, then across warp_n
#pragma unroll
        for (int mi = 0; mi < 2; mi++)
#pragma unroll
            for (int h = 0; h < 2; h++) {
                float s = rs[mi][h];
                s += __shfl_xor_sync(0xffffffffu, s, 1);
                s += __shfl_xor_sync(0xffffffffu, s, 2);
                if (lr == 0)
                    red[(warp_m * 32 + mi * 16 + h * 8 + lq) * 2 + warp_n] = s;
            }
        __syncthreads();
        if (tid < 128) {
            float addv = addsc ? *addsc : 0.f;
            out[rb + tid] = red[tid * 2 + 0] + red[tid * 2 + 1] + addv;
        }
    }
}

// ---------------------------------------------------------------------------
// K4: per-b softmax over T=32 then x_hat = sum_t alpha_t * Xh[b,t,:] -> fp16
// ---------------------------------------------------------------------------
__global__ void softmax_xhat_kernel(const float* __restrict__ e,
                                    const __half* __restrict__ Xh,
                                    __half* __restrict__ xh)
{
    int b = blockIdx.x;
    __shared__ float alpha[TDIM];
    int tid = threadIdx.x;   // 128 threads
    if (tid < 32) {
        float v = e[b * TDIM + tid];
        float m = v;
#pragma unroll
        for (int off = 16; off >= 1; off >>= 1)
            m = fmaxf(m, __shfl_xor_sync(0xffffffffu, m, off));
        float ex = __expf(v - m);
        float s = ex;
#pragma unroll
        for (int off = 16; off >= 1; off >>= 1)
            s += __shfl_xor_sync(0xffffffffu, s, off);
        alpha[tid] = ex / s;
    }
    __syncthreads();
    const __half* Xb = Xh + (size_t)b * TDIM * DDIM + tid * 4;
    float s0 = 0.f, s1 = 0.f, s2 = 0.f, s3 = 0.f;
#pragma unroll
    for (int t = 0; t < TDIM; t++) {
        uint2 raw = *(const uint2*)&Xb[t * DDIM];
        __half2 p0 = *(__half2*)&raw.x;
        __half2 p1 = *(__half2*)&raw.y;
        float a = alpha[t];
        s0 += a * __low2float(p0);  s1 += a * __high2float(p0);
        s2 += a * __low2float(p1);  s3 += a * __high2float(p1);
    }
    __half hh[4];
    hh[0] = __float2half_rn(s0); hh[1] = __float2half_rn(s1);
    hh[2] = __float2half_rn(s2); hh[3] = __float2half_rn(s3);
    ((uint2*)xh)[((size_t)b * DDIM + tid * 4) >> 2] = *(uint2*)hh;
}

// ---------------------------------------------------------------------------
extern "C" void kernel_launch(void* const* d_in, const int* in_sizes, int n_in,
                              void* d_out, int out_size)
{
    const float* X  = (const float*)d_in[0];
    const float* G  = (const float*)d_in[1];
    const float* W1 = (const float*)d_in[2];
    const float* b1 = (const float*)d_in[3];
    const float* w2 = (const float*)d_in[4];
    // d_in[5] = b2: softmax shift-invariant, unused
    const float* M1 = (const float*)d_in[6];
    const float* c1 = (const float*)d_in[7];
    const float* m2 = (const float*)d_in[8];
    const float* c2 = (const float*)d_in[9];
    float* out = (float*)d_out;

    float *E1, *E2, *ebuf;
    cudaGetSymbolAddress((void**)&E1,   E1_buf);
    cudaGetSymbolAddress((void**)&E2,   E2_buf);
    cudaGetSymbolAddress((void**)&ebuf, e_buf);

    __half *Xh, *Gh, *W1h, *M1h, *ghh, *xhh;
    cudaGetSymbolAddress((void**)&Xh,  Xh_buf);
    cudaGetSymbolAddress((void**)&Gh,  Gh_buf);
    cudaGetSymbolAddress((void**)&W1h, W1h_buf);
    cudaGetSymbolAddress((void**)&M1h, M1h_buf);
    cudaGetSymbolAddress((void**)&ghh, ghh_buf);
    cudaGetSymbolAddress((void**)&xhh, xhh_buf);

    cudaFuncSetAttribute((const void*)mma_gemm<5, true>,
                         cudaFuncAttributeMaxDynamicSharedMemorySize, SMEM_BYTES);
    cudaFuncSetAttribute((const void*)mma_gemm<4, true>,
                         cudaFuncAttributeMaxDynamicSharedMemorySize, SMEM_BYTES);
    cudaFuncSetAttribute((const void*)mma_gemm<0, false>,
                         cudaFuncAttributeMaxDynamicSharedMemorySize, SMEM_BYTES);

    // [0] convert X -> fp16
    conv_fp16_kernel<<<(BDIM * TDIM * DDIM / 4) / 256, 256>>>(X, Xh);
    // [1] convert W1 -> fp16
    conv_fp16_kernel<<<(2 * DDIM * HDIM / 4) / 256, 256>>>(W1, W1h);
    // [2] fused: G -> Gh, ghh = mean_k G (single read of G)
    gconv_gmean_kernel<<<(BDIM * DDIM / 4) / 256, 256>>>(G, Gh, ghh);
    // [3] K2: E1 = g_hat @ W1[:512] + b1   (4096 x 1024)
    mma_gemm<0, false><<<dim3(BDIM / 128, HDIM / 64), 256, SMEM_BYTES>>>(
        ghh, W1h, b1, nullptr, nullptr, E1, HDIM);
    // [4] convert M1 -> fp16
    conv_fp16_kernel<<<(2 * DDIM * H2DIM / 4) / 256, 256>>>(M1, M1h);
    // [5] K3: e[b,t] = sum_h relu( X@W1[512:] + E1 ) * w2   (M = 131072)
    mma_gemm<5, true><<<(BDIM * TDIM) / 128, 256, SMEM_BYTES>>>(
        Xh, W1h + (size_t)DDIM * HDIM, E1, w2, nullptr, ebuf, HDIM);
    // [6] softmax over T + x_hat -> fp16
    softmax_xhat_kernel<<<BDIM, 128>>>(ebuf, Xh, xhh);
    // [7] K5: E2 = x_hat @ M1[:512] + c1   (4096 x 2048)
    mma_gemm<0, false><<<dim3(BDIM / 128, H2DIM / 64), 256, SMEM_BYTES>>>(
        xhh, M1h, c1, nullptr, nullptr, E2, H2DIM);
    // [8] K6: logits = sum_j relu( G@M1[512:] + E2 ) * m2 + c2  (M = 65536)
    mma_gemm<4, true><<<(BDIM * KDIM) / 128, 256, SMEM_BYTES>>>(
        Gh, M1h + (size_t)DDIM * H2DIM, E2, m2, c2, out, H2DIM);
}

// round 15
// speedup vs baseline: 1.1939x; 1.1939x over previous
#include <cuda_runtime.h>
#include <cuda_fp16.h>
#include <cstdint>

// Problem constants
#define BDIM  4096
#define TDIM  32
#define KDIM  16
#define DDIM  512
#define HDIM  1024   // = 2*D
#define H2DIM 2048   // = 2*H

// NOTE: harness PTX target is compute_103 (no 'a') -> tcgen05/TMEM rejected.
// Legacy mma.sync HMMA is the tensor path. All GEMMs single-pass fp16.
// Operating point (R10, best=912us): 256 thr/CTA, 2 CTAs/SM, 128 regs,
// BK=32, warp tile 32x64, per-n-tile loop. R15 single delta vs R10:
// pipeline depth 3->4 stages (wait_group 2) to cover DRAM latency on A.

// ---------------------------------------------------------------------------
// Scratch (device globals: allocation-free rule)
// ---------------------------------------------------------------------------
__device__ float E1_buf[BDIM * HDIM];
__device__ float E2_buf[BDIM * H2DIM];
__device__ float e_buf[BDIM * TDIM];

__device__ __half Xh_buf[BDIM * TDIM * DDIM];
__device__ __half Gh_buf[BDIM * KDIM * DDIM];
__device__ __half W1h_buf[2 * DDIM * HDIM];   // full W1 (1024 x 1024)
__device__ __half M1h_buf[2 * DDIM * H2DIM];  // full M1 (1024 x 2048)
__device__ __half ghh_buf[BDIM * DDIM];
__device__ __half xhh_buf[BDIM * DDIM];

// ---------------------------------------------------------------------------
// PTX helpers
// ---------------------------------------------------------------------------
__device__ __forceinline__ void cp16(uint32_t dst, const void* src) {
    asm volatile("cp.async.cg.shared.global [%0], [%1], 16;\n"
                 :: "r"(dst), "l"(src) : "memory");
}
__device__ __forceinline__ void cp_commit() {
    asm volatile("cp.async.commit_group;\n" ::: "memory");
}
__device__ __forceinline__ void cp_wait2() {
    asm volatile("cp.async.wait_group 2;\n" ::: "memory");
}
__device__ __forceinline__ void cp_wait0() {
    asm volatile("cp.async.wait_group 0;\n" ::: "memory");
}
__device__ __forceinline__ void ldsm_x4(unsigned& d0, unsigned& d1, unsigned& d2,
                                        unsigned& d3, uint32_t addr) {
    asm volatile("ldmatrix.sync.aligned.m8n8.x4.shared.b16 {%0,%1,%2,%3}, [%4];\n"
                 : "=r"(d0), "=r"(d1), "=r"(d2), "=r"(d3) : "r"(addr));
}
__device__ __forceinline__ void ldsm_x4_t(unsigned& d0, unsigned& d1, unsigned& d2,
                                          unsigned& d3, uint32_t addr) {
    asm volatile("ldmatrix.sync.aligned.m8n8.x4.trans.shared.b16 {%0,%1,%2,%3}, [%4];\n"
                 : "=r"(d0), "=r"(d1), "=r"(d2), "=r"(d3) : "r"(addr));
}
__device__ __forceinline__ void mma16816(float c[4], const unsigned a[4], const unsigned b[2]) {
    asm volatile(
        "mma.sync.aligned.m16n8k16.row.col.f32.f16.f16.f32 "
        "{%0,%1,%2,%3}, {%4,%5,%6,%7}, {%8,%9}, {%0,%1,%2,%3};\n"
        : "+f"(c[0]), "+f"(c[1]), "+f"(c[2]), "+f"(c[3])
        : "r"(a[0]), "r"(a[1]), "r"(a[2]), "r"(a[3]), "r"(b[0]), "r"(b[1]));
}

// ---------------------------------------------------------------------------
// convert-only: hi = fp16(x)
// ---------------------------------------------------------------------------
__global__ void conv_fp16_kernel(const float* __restrict__ src,
                                 __half* __restrict__ hi)
{
    int i = blockIdx.x * blockDim.x + threadIdx.x;
    float4 v = ((const float4*)src)[i];
    __half h[4];
    h[0] = __float2half_rn(v.x); h[1] = __float2half_rn(v.y);
    h[2] = __float2half_rn(v.z); h[3] = __float2half_rn(v.w);
    ((uint2*)hi)[i] = *(uint2*)h;
}

// ---------------------------------------------------------------------------
// fused: G -> Gh (fp16) AND ghh = fp16(mean_k G)   (single read of G)
// ---------------------------------------------------------------------------
__global__ void gconv_gmean_kernel(const float* __restrict__ G,
                                   __half* __restrict__ Gh,
                                   __half* __restrict__ ghh)
{
    int idx = blockIdx.x * blockDim.x + threadIdx.x;   // over B * (D/4)
    int b  = idx >> 7;
    int ch = idx & 127;
    const float4* gp = (const float4*)(G + (size_t)b * KDIM * DDIM + ch * 4);
    float4 acc = make_float4(0.f, 0.f, 0.f, 0.f);
#pragma unroll
    for (int k = 0; k < KDIM; k++) {
        float4 v = gp[k * (DDIM / 4)];
        __half h[4];
        h[0] = __float2half_rn(v.x); h[1] = __float2half_rn(v.y);
        h[2] = __float2half_rn(v.z); h[3] = __float2half_rn(v.w);
        ((uint2*)Gh)[((size_t)b * KDIM * DDIM + (size_t)k * DDIM) / 4 + ch] = *(uint2*)h;
        acc.x += v.x; acc.y += v.y; acc.z += v.z; acc.w += v.w;
    }
    const float inv = 1.0f / KDIM;
    __half m[4];
    m[0] = __float2half_rn(acc.x * inv); m[1] = __float2half_rn(acc.y * inv);
    m[2] = __float2half_rn(acc.z * inv); m[3] = __float2half_rn(acc.w * inv);
    ((uint2*)ghh)[idx] = *(uint2*)m;
}

// ---------------------------------------------------------------------------
// fp16 tensor-core GEMM. BM=128, BN=128, BK=32, 8 warps (4m x 2n),
// warp tile 32x64. 4-stage cp.async pipeline (wait_group 2), per n-tile.
// REDUCE=true : out[row] = sum_n relu(acc + Eb[row>>RPB_SHIFT, n]) * wvec[n] (+sc)
//               grid = (M/128), loops all N tiles internally.
// REDUCE=false: out[row,col] = acc + bias[col]; grid = (M/128, N/128).
// ---------------------------------------------------------------------------
constexpr int ASZ = 128 * 40 * 2;     // one A stage (bytes)
constexpr int BSZ = 32 * 136 * 2;     // one B stage (bytes)
constexpr int NSTG = 4;
constexpr int SMEM_BYTES = NSTG * (ASZ + BSZ) + 128 * 2 * 4;
constexpr int NKT = DDIM / 32;        // 16 k-tiles per n-tile

template <int RPB_SHIFT, bool REDUCE>
__global__ void __launch_bounds__(256, 2) mma_gemm(
    const __half* __restrict__ Ah,
    const __half* __restrict__ Bh,
    const float* __restrict__ EbOrBias,
    const float* __restrict__ wvec,
    const float* __restrict__ addsc,
    float* __restrict__ out,
    int N)
{
    extern __shared__ __align__(16) char smraw[];
    float* red = (float*)(smraw + NSTG * (ASZ + BSZ));   // [128][2]

    const int tid  = threadIdx.x;
    const int lane = tid & 31;
    const int wid  = tid >> 5;
    const int warp_m = wid & 3;       // 4 warps in M
    const int warp_n = wid >> 2;      // 2 warps in N
    const int lq = lane >> 2, lr = lane & 3;
    const int rb = blockIdx.x * 128;

    const uint32_t uS = (uint32_t)__cvta_generic_to_shared(smraw);
    const uint32_t uA = uS;
    const uint32_t uB = uS + NSTG * ASZ;

    // staging chunk coords (A: 2 chunks, B: 2 chunks per thread per tile)
    int am[2], ak[2], bk[2], bn[2];
#pragma unroll
    for (int c = 0; c < 2; c++) {
        int cid = tid + c * 256;
        am[c] = cid >> 2;  ak[c] = (cid & 3) << 3;
        bk[c] = cid >> 4;  bn[c] = (cid & 15) << 3;
    }

    // ldmatrix per-lane address components
    const uint32_t a_frag_off =
        (uint32_t)(((warp_m * 32 + (lane & 15)) * 40 + ((lane & 16) >> 1)) * 2);
    const uint32_t b_frag_off =
        (uint32_t)(((lane & 15) * 136 + warp_n * 64 + ((lane & 16) >> 1)) * 2);

    float rs[2][2] = {{0.f, 0.f}, {0.f, 0.f}};
    const int ntiles = REDUCE ? (N >> 7) : 1;

    for (int nt = 0; nt < ntiles; nt++) {
        const int cb = REDUCE ? (nt << 7) : ((int)blockIdx.y << 7);

        float c[2][8][4] = {};

        auto stage = [&](int buf, int kt) {
            const int koff = kt << 5;
            const uint32_t adst0 = uA + (uint32_t)(buf * ASZ);
            const uint32_t bdst0 = uB + (uint32_t)(buf * BSZ);
#pragma unroll
            for (int cc = 0; cc < 2; cc++) {
                cp16(adst0 + (uint32_t)((am[cc] * 40 + ak[cc]) * 2),
                     Ah + (size_t)(rb + am[cc]) * DDIM + koff + ak[cc]);
                cp16(bdst0 + (uint32_t)((bk[cc] * 136 + bn[cc]) * 2),
                     Bh + (size_t)(koff + bk[cc]) * N + cb + bn[cc]);
            }
        };

        // prologue: 3 stages in flight
        stage(0, 0); cp_commit();
        stage(1, 1); cp_commit();
        stage(2, 2); cp_commit();

        for (int kt = 0; kt < NKT; kt++) {
            cp_wait2();               // tile kt resident (<=2 groups pending)
            __syncthreads();
            if (kt + 3 < NKT) stage((kt + 3) & (NSTG - 1), kt + 3);
            cp_commit();              // empty commit keeps group count aligned

            const int buf = kt & (NSTG - 1);
            const uint32_t Ahb = uA + (uint32_t)(buf * ASZ) + a_frag_off;
            const uint32_t Bhb = uB + (uint32_t)(buf * BSZ) + b_frag_off;

#pragma unroll
            for (int kk = 0; kk < 32; kk += 16) {
                unsigned ah[2][4], bh[8][2];
#pragma unroll
                for (int mi = 0; mi < 2; mi++)
                    ldsm_x4(ah[mi][0], ah[mi][1], ah[mi][2], ah[mi][3],
                            Ahb + (uint32_t)((mi * 16 * 40 + kk) * 2));
#pragma unroll
                for (int gg = 0; gg < 4; gg++)
                    ldsm_x4_t(bh[2*gg][0], bh[2*gg][1], bh[2*gg+1][0], bh[2*gg+1][1],
                              Bhb + (uint32_t)((kk * 136 + gg * 16) * 2));
#pragma unroll
                for (int mi = 0; mi < 2; mi++)
#pragma unroll
                    for (int ni = 0; ni < 8; ni++)
                        mma16816(c[mi][ni], ah[mi], bh[ni]);
            }
        }
        cp_wait0();        // drain (empty tail groups) before buffer reuse
        __syncthreads();   // protect stage buffers before next nt prologue

        if (REDUCE) {
            // fused epilogue: relu(acc + Eb) . wvec
#pragma unroll
            for (int mi = 0; mi < 2; mi++) {
                int row0 = rb + warp_m * 32 + mi * 16 + lq;
                int row1 = row0 + 8;
                const float* Eb0 = EbOrBias + (size_t)(row0 >> RPB_SHIFT) * N;
                const float* Eb1 = EbOrBias + (size_t)(row1 >> RPB_SHIFT) * N;
#pragma unroll
                for (int ni = 0; ni < 8; ni++) {
                    int col = cb + warp_n * 64 + ni * 8 + lr * 2;
                    float2 e0 = *(const float2*)&Eb0[col];
                    float2 e1 = *(const float2*)&Eb1[col];
                    float2 wv = *(const float2*)&wvec[col];
                    rs[mi][0] += fmaxf(c[mi][ni][0] + e0.x, 0.f) * wv.x
                               + fmaxf(c[mi][ni][1] + e0.y, 0.f) * wv.y;
                    rs[mi][1] += fmaxf(c[mi][ni][2] + e1.x, 0.f) * wv.x
                               + fmaxf(c[mi][ni][3] + e1.y, 0.f) * wv.y;
                }
            }
        } else {
            // plain store epilogue: C = acc + bias
#pragma unroll
            for (int mi = 0; mi < 2; mi++) {
                int row0 = rb + warp_m * 32 + mi * 16 + lq;
                int row1 = row0 + 8;
#pragma unroll
                for (int ni = 0; ni < 8; ni++) {
                    int col = cb + warp_n * 64 + ni * 8 + lr * 2;
                    float2 bv = *(const float2*)&EbOrBias[col];
                    float2 o0, o1;
                    o0.x = c[mi][ni][0] + bv.x; o0.y = c[mi][ni][1] + bv.y;
                    o1.x = c[mi][ni][2] + bv.x; o1.y = c[mi][ni][3] + bv.y;
                    *(float2*)&out[(size_t)row0 * N + col] = o0;
                    *(float2*)&out[(size_t)row1 * N + col] = o1;
                }
            }
        }
    }

    if (REDUCE) {
        // reduce across the 4 lanes sharing each row, then across warp_n
#pragma unroll
        for (int mi = 0; mi < 2; mi++)
#pragma unroll
            for (int h = 0; h < 2; h++) {
                float s = rs[mi][h];
                s += __shfl_xor_sync(0xffffffffu, s, 1);
                s += __shfl_xor_sync(0xffffffffu, s, 2);
                if (lr == 0)
                    red[(warp_m * 32 + mi * 16 + h * 8 + lq) * 2 + warp_n] = s;
            }
        __syncthreads();
        if (tid < 128) {
            float addv = addsc ? *addsc : 0.f;
            out[rb + tid] = red[tid * 2 + 0] + red[tid * 2 + 1] + addv;
        }
    }
}

// ---------------------------------------------------------------------------
// K4: per-b softmax over T=32 then x_hat = sum_t alpha_t * Xh[b,t,:] -> fp16
// ---------------------------------------------------------------------------
__global__ void softmax_xhat_kernel(const float* __restrict__ e,
                                    const __half* __restrict__ Xh,
                                    __half* __restrict__ xh)
{
    int b = blockIdx.x;
    __shared__ float alpha[TDIM];
    int tid = threadIdx.x;   // 128 threads
    if (tid < 32) {
        float v = e[b * TDIM + tid];
        float m = v;
#pragma unroll
        for (int off = 16; off >= 1; off >>= 1)
            m = fmaxf(m, __shfl_xor_sync(0xffffffffu, m, off));
        float ex = __expf(v - m);
        float s = ex;
#pragma unroll
        for (int off = 16; off >= 1; off >>= 1)
            s += __shfl_xor_sync(0xffffffffu, s, off);
        alpha[tid] = ex / s;
    }
    __syncthreads();
    const __half* Xb = Xh + (size_t)b * TDIM * DDIM + tid * 4;
    float s0 = 0.f, s1 = 0.f, s2 = 0.f, s3 = 0.f;
#pragma unroll
    for (int t = 0; t < TDIM; t++) {
        uint2 raw = *(const uint2*)&Xb[t * DDIM];
        __half2 p0 = *(__half2*)&raw.x;
        __half2 p1 = *(__half2*)&raw.y;
        float a = alpha[t];
        s0 += a * __low2float(p0);  s1 += a * __high2float(p0);
        s2 += a * __low2float(p1);  s3 += a * __high2float(p1);
    }
    __half hh[4];
    hh[0] = __float2half_rn(s0); hh[1] = __float2half_rn(s1);
    hh[2] = __float2half_rn(s2); hh[3] = __float2half_rn(s3);
    ((uint2*)xh)[((size_t)b * DDIM + tid * 4) >> 2] = *(uint2*)hh;
}

// ---------------------------------------------------------------------------
extern "C" void kernel_launch(void* const* d_in, const int* in_sizes, int n_in,
                              void* d_out, int out_size)
{
    const float* X  = (const float*)d_in[0];
    const float* G  = (const float*)d_in[1];
    const float* W1 = (const float*)d_in[2];
    const float* b1 = (const float*)d_in[3];
    const float* w2 = (const float*)d_in[4];
    // d_in[5] = b2: softmax shift-invariant, unused
    const float* M1 = (const float*)d_in[6];
    const float* c1 = (const float*)d_in[7];
    const float* m2 = (const float*)d_in[8];
    const float* c2 = (const float*)d_in[9];
    float* out = (float*)d_out;

    float *E1, *E2, *ebuf;
    cudaGetSymbolAddress((void**)&E1,   E1_buf);
    cudaGetSymbolAddress((void**)&E2,   E2_buf);
    cudaGetSymbolAddress((void**)&ebuf, e_buf);

    __half *Xh, *Gh, *W1h, *M1h, *ghh, *xhh;
    cudaGetSymbolAddress((void**)&Xh,  Xh_buf);
    cudaGetSymbolAddress((void**)&Gh,  Gh_buf);
    cudaGetSymbolAddress((void**)&W1h, W1h_buf);
    cudaGetSymbolAddress((void**)&M1h, M1h_buf);
    cudaGetSymbolAddress((void**)&ghh, ghh_buf);
    cudaGetSymbolAddress((void**)&xhh, xhh_buf);

    cudaFuncSetAttribute((const void*)mma_gemm<5, true>,
                         cudaFuncAttributeMaxDynamicSharedMemorySize, SMEM_BYTES);
    cudaFuncSetAttribute((const void*)mma_gemm<4, true>,
                         cudaFuncAttributeMaxDynamicSharedMemorySize, SMEM_BYTES);
    cudaFuncSetAttribute((const void*)mma_gemm<0, false>,
                         cudaFuncAttributeMaxDynamicSharedMemorySize, SMEM_BYTES);

    // [0] convert X -> fp16
    conv_fp16_kernel<<<(BDIM * TDIM * DDIM / 4) / 256, 256>>>(X, Xh);
    // [1] convert W1 -> fp16
    conv_fp16_kernel<<<(2 * DDIM * HDIM / 4) / 256, 256>>>(W1, W1h);
    // [2] fused: G -> Gh, ghh = mean_k G (single read of G)
    gconv_gmean_kernel<<<(BDIM * DDIM / 4) / 256, 256>>>(G, Gh, ghh);
    // [3] K2: E1 = g_hat @ W1[:512] + b1   (4096 x 1024)
    mma_gemm<0, false><<<dim3(BDIM / 128, HDIM / 128), 256, SMEM_BYTES>>>(
        ghh, W1h, b1, nullptr, nullptr, E1, HDIM);
    // [4] convert M1 -> fp16
    conv_fp16_kernel<<<(2 * DDIM * H2DIM / 4) / 256, 256>>>(M1, M1h);
    // [5] K3: e[b,t] = sum_h relu( X@W1[512:] + E1 ) * w2   (M = 131072)
    mma_gemm<5, true><<<(BDIM * TDIM) / 128, 256, SMEM_BYTES>>>(
        Xh, W1h + (size_t)DDIM * HDIM, E1, w2, nullptr, ebuf, HDIM);
    // [6] softmax over T + x_hat -> fp16
    softmax_xhat_kernel<<<BDIM, 128>>>(ebuf, Xh, xhh);
    // [7] K5: E2 = x_hat @ M1[:512] + c1   (4096 x 2048)
    mma_gemm<0, false><<<dim3(BDIM / 128, H2DIM / 128), 256, SMEM_BYTES>>>(
        xhh, M1h, c1, nullptr, nullptr, E2, H2DIM);
    // [8] K6: logits = sum_j relu( G@M1[512:] + E2 ) * m2 + c2  (M = 65536)
    mma_gemm<4, true><<<(BDIM * KDIM) / 128, 256, SMEM_BYTES>>>(
        Gh, M1h + (size_t)DDIM * H2DIM, E2, m2, c2, out, H2DIM);
}

// round 16
// speedup vs baseline: 1.4038x; 1.1758x over previous
#include <cuda_runtime.h>
#include <cuda_fp16.h>
#include <cstdint>

// Problem constants
#define BDIM  4096
#define TDIM  32
#define KDIM  16
#define DDIM  512
#define HDIM  1024   // = 2*D
#define H2DIM 2048   // = 2*H

// NOTE: harness PTX target is compute_103 (no 'a') -> tcgen05/TMEM rejected.
// Legacy mma.sync HMMA is the tensor path. All GEMMs single-pass fp16.
// Mainloop locked at the R10 optimum: 256 thr/CTA, 2 CTAs/SM, 128 regs,
// BK=32, warp tile 32x64, 3-stage/wait-1 pipeline.
// R16 delta: split-N grids (x = n-tile fastest) so A streams DRAM once and
// is L2-shared across n-tiles; REDUCE writes partials, tiny final-sum kernel.

// ---------------------------------------------------------------------------
// Scratch (device globals: allocation-free rule)
// ---------------------------------------------------------------------------
__device__ float E1_buf[BDIM * HDIM];
__device__ float E2_buf[BDIM * H2DIM];
__device__ float e_buf[BDIM * TDIM];
__device__ float part_buf[16 * BDIM * TDIM / 2 * 2];   // 16*65536 = 8*131072 = 1M floats

__device__ __half Xh_buf[BDIM * TDIM * DDIM];
__device__ __half Gh_buf[BDIM * KDIM * DDIM];
__device__ __half W1h_buf[2 * DDIM * HDIM];   // full W1 (1024 x 1024)
__device__ __half M1h_buf[2 * DDIM * H2DIM];  // full M1 (1024 x 2048)
__device__ __half ghh_buf[BDIM * DDIM];
__device__ __half xhh_buf[BDIM * DDIM];

// ---------------------------------------------------------------------------
// PTX helpers
// ---------------------------------------------------------------------------
__device__ __forceinline__ void cp16(uint32_t dst, const void* src) {
    asm volatile("cp.async.cg.shared.global [%0], [%1], 16;\n"
                 :: "r"(dst), "l"(src) : "memory");
}
__device__ __forceinline__ void cp_commit() {
    asm volatile("cp.async.commit_group;\n" ::: "memory");
}
__device__ __forceinline__ void cp_wait1() {
    asm volatile("cp.async.wait_group 1;\n" ::: "memory");
}
__device__ __forceinline__ void ldsm_x4(unsigned& d0, unsigned& d1, unsigned& d2,
                                        unsigned& d3, uint32_t addr) {
    asm volatile("ldmatrix.sync.aligned.m8n8.x4.shared.b16 {%0,%1,%2,%3}, [%4];\n"
                 : "=r"(d0), "=r"(d1), "=r"(d2), "=r"(d3) : "r"(addr));
}
__device__ __forceinline__ void ldsm_x4_t(unsigned& d0, unsigned& d1, unsigned& d2,
                                          unsigned& d3, uint32_t addr) {
    asm volatile("ldmatrix.sync.aligned.m8n8.x4.trans.shared.b16 {%0,%1,%2,%3}, [%4];\n"
                 : "=r"(d0), "=r"(d1), "=r"(d2), "=r"(d3) : "r"(addr));
}
__device__ __forceinline__ void mma16816(float c[4], const unsigned a[4], const unsigned b[2]) {
    asm volatile(
        "mma.sync.aligned.m16n8k16.row.col.f32.f16.f16.f32 "
        "{%0,%1,%2,%3}, {%4,%5,%6,%7}, {%8,%9}, {%0,%1,%2,%3};\n"
        : "+f"(c[0]), "+f"(c[1]), "+f"(c[2]), "+f"(c[3])
        : "r"(a[0]), "r"(a[1]), "r"(a[2]), "r"(a[3]), "r"(b[0]), "r"(b[1]));
}

// ---------------------------------------------------------------------------
// convert-only: hi = fp16(x)
// ---------------------------------------------------------------------------
__global__ void conv_fp16_kernel(const float* __restrict__ src,
                                 __half* __restrict__ hi)
{
    int i = blockIdx.x * blockDim.x + threadIdx.x;
    float4 v = ((const float4*)src)[i];
    __half h[4];
    h[0] = __float2half_rn(v.x); h[1] = __float2half_rn(v.y);
    h[2] = __float2half_rn(v.z); h[3] = __float2half_rn(v.w);
    ((uint2*)hi)[i] = *(uint2*)h;
}

// ---------------------------------------------------------------------------
// fused: G -> Gh (fp16) AND ghh = fp16(mean_k G)   (single read of G)
// ---------------------------------------------------------------------------
__global__ void gconv_gmean_kernel(const float* __restrict__ G,
                                   __half* __restrict__ Gh,
                                   __half* __restrict__ ghh)
{
    int idx = blockIdx.x * blockDim.x + threadIdx.x;   // over B * (D/4)
    int b  = idx >> 7;
    int ch = idx & 127;
    const float4* gp = (const float4*)(G + (size_t)b * KDIM * DDIM + ch * 4);
    float4 acc = make_float4(0.f, 0.f, 0.f, 0.f);
#pragma unroll
    for (int k = 0; k < KDIM; k++) {
        float4 v = gp[k * (DDIM / 4)];
        __half h[4];
        h[0] = __float2half_rn(v.x); h[1] = __float2half_rn(v.y);
        h[2] = __float2half_rn(v.z); h[3] = __float2half_rn(v.w);
        ((uint2*)Gh)[((size_t)b * KDIM * DDIM + (size_t)k * DDIM) / 4 + ch] = *(uint2*)h;
        acc.x += v.x; acc.y += v.y; acc.z += v.z; acc.w += v.w;
    }
    const float inv = 1.0f / KDIM;
    __half m[4];
    m[0] = __float2half_rn(acc.x * inv); m[1] = __float2half_rn(acc.y * inv);
    m[2] = __float2half_rn(acc.z * inv); m[3] = __float2half_rn(acc.w * inv);
    ((uint2*)ghh)[idx] = *(uint2*)m;
}

// ---------------------------------------------------------------------------
// fp16 tensor-core GEMM, one 128x128 output tile per CTA (R10 mainloop).
// grid = (N/128, M/128); x (n-tile) fastest -> CTAs sharing rb are adjacent
// and share the A tile through L2.
// REDUCE=true : partial[row] = sum_{n in tile} relu(acc + Eb[row>>SHIFT, n])*wvec[n]
//               written to out[cb_tile * M + row]  (part buffer)
// REDUCE=false: out[row,col] = acc + bias[col]
// ---------------------------------------------------------------------------
constexpr int ASZ = 128 * 40 * 2;     // one A stage (bytes)
constexpr int BSZ = 32 * 136 * 2;     // one B stage (bytes)
constexpr int NSTG = 3;
constexpr int SMEM_BYTES = NSTG * (ASZ + BSZ) + 128 * 2 * 4;
constexpr int NKT = DDIM / 32;        // 16 k-tiles

template <int RPB_SHIFT, bool REDUCE>
__global__ void __launch_bounds__(256, 2) mma_gemm(
    const __half* __restrict__ Ah,
    const __half* __restrict__ Bh,
    const float* __restrict__ EbOrBias,
    const float* __restrict__ wvec,
    float* __restrict__ out,
    int N)
{
    extern __shared__ __align__(16) char smraw[];
    float* red = (float*)(smraw + NSTG * (ASZ + BSZ));   // [128][2]

    const int tid  = threadIdx.x;
    const int lane = tid & 31;
    const int wid  = tid >> 5;
    const int warp_m = wid & 3;       // 4 warps in M
    const int warp_n = wid >> 2;      // 2 warps in N
    const int lq = lane >> 2, lr = lane & 3;
    const int rb = (int)blockIdx.y << 7;
    const int cb = (int)blockIdx.x << 7;

    const uint32_t uS = (uint32_t)__cvta_generic_to_shared(smraw);
    const uint32_t uA = uS;
    const uint32_t uB = uS + NSTG * ASZ;

    // staging chunk coords (A: 2 chunks, B: 2 chunks per thread per tile)
    int am[2], ak[2], bk[2], bn[2];
#pragma unroll
    for (int c = 0; c < 2; c++) {
        int cid = tid + c * 256;
        am[c] = cid >> 2;  ak[c] = (cid & 3) << 3;
        bk[c] = cid >> 4;  bn[c] = (cid & 15) << 3;
    }

    // ldmatrix per-lane address components
    const uint32_t a_frag_off =
        (uint32_t)(((warp_m * 32 + (lane & 15)) * 40 + ((lane & 16) >> 1)) * 2);
    const uint32_t b_frag_off =
        (uint32_t)(((lane & 15) * 136 + warp_n * 64 + ((lane & 16) >> 1)) * 2);

    float c[2][8][4] = {};

    auto stage = [&](int buf, int kt) {
        const int koff = kt << 5;
        const uint32_t adst0 = uA + (uint32_t)(buf * ASZ);
        const uint32_t bdst0 = uB + (uint32_t)(buf * BSZ);
#pragma unroll
        for (int cc = 0; cc < 2; cc++) {
            cp16(adst0 + (uint32_t)((am[cc] * 40 + ak[cc]) * 2),
                 Ah + (size_t)(rb + am[cc]) * DDIM + koff + ak[cc]);
            cp16(bdst0 + (uint32_t)((bk[cc] * 136 + bn[cc]) * 2),
                 Bh + (size_t)(koff + bk[cc]) * N + cb + bn[cc]);
        }
    };

    stage(0, 0);
    cp_commit();

    for (int kt = 0; kt < NKT; kt++) {
        if (kt < NKT - 1) stage((kt + 1) % NSTG, kt + 1);
        cp_commit();
        cp_wait1();
        __syncthreads();

        const int buf = kt % NSTG;
        const uint32_t Ahb = uA + (uint32_t)(buf * ASZ) + a_frag_off;
        const uint32_t Bhb = uB + (uint32_t)(buf * BSZ) + b_frag_off;

#pragma unroll
        for (int kk = 0; kk < 32; kk += 16) {
            unsigned ah[2][4], bh[8][2];
#pragma unroll
            for (int mi = 0; mi < 2; mi++)
                ldsm_x4(ah[mi][0], ah[mi][1], ah[mi][2], ah[mi][3],
                        Ahb + (uint32_t)((mi * 16 * 40 + kk) * 2));
#pragma unroll
            for (int gg = 0; gg < 4; gg++)
                ldsm_x4_t(bh[2*gg][0], bh[2*gg][1], bh[2*gg+1][0], bh[2*gg+1][1],
                          Bhb + (uint32_t)((kk * 136 + gg * 16) * 2));
#pragma unroll
            for (int mi = 0; mi < 2; mi++)
#pragma unroll
                for (int ni = 0; ni < 8; ni++)
                    mma16816(c[mi][ni], ah[mi], bh[ni]);
        }
        __syncthreads();
    }

    if (REDUCE) {
        // fused epilogue: relu(acc + Eb) . wvec -> partial row sums
        float rs[2][2] = {{0.f, 0.f}, {0.f, 0.f}};
#pragma unroll
        for (int mi = 0; mi < 2; mi++) {
            int row0 = rb + warp_m * 32 + mi * 16 + lq;
            int row1 = row0 + 8;
            const float* Eb0 = EbOrBias + (size_t)(row0 >> RPB_SHIFT) * N;
            const float* Eb1 = EbOrBias + (size_t)(row1 >> RPB_SHIFT) * N;
#pragma unroll
            for (int ni = 0; ni < 8; ni++) {
                int col = cb + warp_n * 64 + ni * 8 + lr * 2;
                float2 e0 = *(const float2*)&Eb0[col];
                float2 e1 = *(const float2*)&Eb1[col];
                float2 wv = *(const float2*)&wvec[col];
                rs[mi][0] += fmaxf(c[mi][ni][0] + e0.x, 0.f) * wv.x
                           + fmaxf(c[mi][ni][1] + e0.y, 0.f) * wv.y;
                rs[mi][1] += fmaxf(c[mi][ni][2] + e1.x, 0.f) * wv.x
                           + fmaxf(c[mi][ni][3] + e1.y, 0.f) * wv.y;
            }
        }
        // reduce across the 4 lanes sharing each row, then across warp_n
#pragma unroll
        for (int mi = 0; mi < 2; mi++)
#pragma unroll
            for (int h = 0; h < 2; h++) {
                float s = rs[mi][h];
                s += __shfl_xor_sync(0xffffffffu, s, 1);
                s += __shfl_xor_sync(0xffffffffu, s, 2);
                if (lr == 0)
                    red[(warp_m * 32 + mi * 16 + h * 8 + lq) * 2 + warp_n] = s;
            }
        __syncthreads();
        if (tid < 128) {
            size_t M = (size_t)gridDim.y << 7;
            out[(size_t)blockIdx.x * M + rb + tid] =
                red[tid * 2 + 0] + red[tid * 2 + 1];
        }
    } else {
        // plain store epilogue: C = acc + bias
#pragma unroll
        for (int mi = 0; mi < 2; mi++) {
            int row0 = rb + warp_m * 32 + mi * 16 + lq;
            int row1 = row0 + 8;
#pragma unroll
            for (int ni = 0; ni < 8; ni++) {
                int col = cb + warp_n * 64 + ni * 8 + lr * 2;
                float2 bv = *(const float2*)&EbOrBias[col];
                float2 o0, o1;
                o0.x = c[mi][ni][0] + bv.x; o0.y = c[mi][ni][1] + bv.y;
                o1.x = c[mi][ni][2] + bv.x; o1.y = c[mi][ni][3] + bv.y;
                *(float2*)&out[(size_t)row0 * N + col] = o0;
                *(float2*)&out[(size_t)row1 * N + col] = o1;
            }
        }
    }
}

// ---------------------------------------------------------------------------
// final reduction: out[i] = sum_nt part[nt*M + i] (+ *addsc), float4 per thread
// ---------------------------------------------------------------------------
template <int NT>
__global__ void reduce_final_kernel(const float* __restrict__ part,
                                    float* __restrict__ out,
                                    const float* __restrict__ addsc,
                                    int M)
{
    int i = blockIdx.x * blockDim.x + threadIdx.x;    // over M/4
    const float4* p = (const float4*)part;
    float4 s = p[i];
#pragma unroll
    for (int nt = 1; nt < NT; nt++) {
        float4 v = p[(size_t)nt * (M >> 2) + i];
        s.x += v.x; s.y += v.y; s.z += v.z; s.w += v.w;
    }
    if (addsc) {
        float a = *addsc;
        s.x += a; s.y += a; s.z += a; s.w += a;
    }
    ((float4*)out)[i] = s;
}

// ---------------------------------------------------------------------------
// K4: per-b softmax over T=32 then x_hat = sum_t alpha_t * Xh[b,t,:] -> fp16
// ---------------------------------------------------------------------------
__global__ void softmax_xhat_kernel(const float* __restrict__ e,
                                    const __half* __restrict__ Xh,
                                    __half* __restrict__ xh)
{
    int b = blockIdx.x;
    __shared__ float alpha[TDIM];
    int tid = threadIdx.x;   // 128 threads
    if (tid < 32) {
        float v = e[b * TDIM + tid];
        float m = v;
#pragma unroll
        for (int off = 16; off >= 1; off >>= 1)
            m = fmaxf(m, __shfl_xor_sync(0xffffffffu, m, off));
        float ex = __expf(v - m);
        float s = ex;
#pragma unroll
        for (int off = 16; off >= 1; off >>= 1)
            s += __shfl_xor_sync(0xffffffffu, s, off);
        alpha[tid] = ex / s;
    }
    __syncthreads();
    const __half* Xb = Xh + (size_t)b * TDIM * DDIM + tid * 4;
    float s0 = 0.f, s1 = 0.f, s2 = 0.f, s3 = 0.f;
#pragma unroll
    for (int t = 0; t < TDIM; t++) {
        uint2 raw = *(const uint2*)&Xb[t * DDIM];
        __half2 p0 = *(__half2*)&raw.x;
        __half2 p1 = *(__half2*)&raw.y;
        float a = alpha[t];
        s0 += a * __low2float(p0);  s1 += a * __high2float(p0);
        s2 += a * __low2float(p1);  s3 += a * __high2float(p1);
    }
    __half hh[4];
    hh[0] = __float2half_rn(s0); hh[1] = __float2half_rn(s1);
    hh[2] = __float2half_rn(s2); hh[3] = __float2half_rn(s3);
    ((uint2*)xh)[((size_t)b * DDIM + tid * 4) >> 2] = *(uint2*)hh;
}

// ---------------------------------------------------------------------------
extern "C" void kernel_launch(void* const* d_in, const int* in_sizes, int n_in,
                              void* d_out, int out_size)
{
    const float* X  = (const float*)d_in[0];
    const float* G  = (const float*)d_in[1];
    const float* W1 = (const float*)d_in[2];
    const float* b1 = (const float*)d_in[3];
    const float* w2 = (const float*)d_in[4];
    // d_in[5] = b2: softmax shift-invariant, unused
    const float* M1 = (const float*)d_in[6];
    const float* c1 = (const float*)d_in[7];
    const float* m2 = (const float*)d_in[8];
    const float* c2 = (const float*)d_in[9];
    float* out = (float*)d_out;

    float *E1, *E2, *ebuf, *part;
    cudaGetSymbolAddress((void**)&E1,   E1_buf);
    cudaGetSymbolAddress((void**)&E2,   E2_buf);
    cudaGetSymbolAddress((void**)&ebuf, e_buf);
    cudaGetSymbolAddress((void**)&part, part_buf);

    __half *Xh, *Gh, *W1h, *M1h, *ghh, *xhh;
    cudaGetSymbolAddress((void**)&Xh,  Xh_buf);
    cudaGetSymbolAddress((void**)&Gh,  Gh_buf);
    cudaGetSymbolAddress((void**)&W1h, W1h_buf);
    cudaGetSymbolAddress((void**)&M1h, M1h_buf);
    cudaGetSymbolAddress((void**)&ghh, ghh_buf);
    cudaGetSymbolAddress((void**)&xhh, xhh_buf);

    cudaFuncSetAttribute((const void*)mma_gemm<5, true>,
                         cudaFuncAttributeMaxDynamicSharedMemorySize, SMEM_BYTES);
    cudaFuncSetAttribute((const void*)mma_gemm<4, true>,
                         cudaFuncAttributeMaxDynamicSharedMemorySize, SMEM_BYTES);
    cudaFuncSetAttribute((const void*)mma_gemm<0, false>,
                         cudaFuncAttributeMaxDynamicSharedMemorySize, SMEM_BYTES);

    // [0] convert X -> fp16
    conv_fp16_kernel<<<(BDIM * TDIM * DDIM / 4) / 256, 256>>>(X, Xh);
    // [1] convert W1 -> fp16
    conv_fp16_kernel<<<(2 * DDIM * HDIM / 4) / 256, 256>>>(W1, W1h);
    // [2] fused: G -> Gh, ghh = mean_k G (single read of G)
    gconv_gmean_kernel<<<(BDIM * DDIM / 4) / 256, 256>>>(G, Gh, ghh);
    // [3] K2: E1 = g_hat @ W1[:512] + b1   (4096 x 1024)
    mma_gemm<0, false><<<dim3(HDIM / 128, BDIM / 128), 256, SMEM_BYTES>>>(
        ghh, W1h, b1, nullptr, E1, HDIM);
    // [4] convert M1 -> fp16
    conv_fp16_kernel<<<(2 * DDIM * H2DIM / 4) / 256, 256>>>(M1, M1h);
    // [5] K3: partial e sums over each 128-col slice   (M = 131072, 8 n-tiles)
    mma_gemm<5, true><<<dim3(HDIM / 128, (BDIM * TDIM) / 128), 256, SMEM_BYTES>>>(
        Xh, W1h + (size_t)DDIM * HDIM, E1, w2, part, HDIM);
    // [6] e = sum of 8 partials
    reduce_final_kernel<8><<<(BDIM * TDIM / 4) / 256, 256>>>(
        part, ebuf, nullptr, BDIM * TDIM);
    // [7] softmax over T + x_hat -> fp16
    softmax_xhat_kernel<<<BDIM, 128>>>(ebuf, Xh, xhh);
    // [8] K5: E2 = x_hat @ M1[:512] + c1   (4096 x 2048)
    mma_gemm<0, false><<<dim3(H2DIM / 128, BDIM / 128), 256, SMEM_BYTES>>>(
        xhh, M1h, c1, nullptr, E2, H2DIM);
    // [9] K6: partial logit sums   (M = 65536, 16 n-tiles)
    mma_gemm<4, true><<<dim3(H2DIM / 128, (BDIM * KDIM) / 128), 256, SMEM_BYTES>>>(
        Gh, M1h + (size_t)DDIM * H2DIM, E2, m2, part, H2DIM);
    // [10] logits = sum of 16 partials + c2
    reduce_final_kernel<16><<<(BDIM * KDIM / 4) / 256, 256>>>(
        part, out, c2, BDIM * KDIM);
}

// round 17
// speedup vs baseline: 1.4808x; 1.0548x over previous
#include <cuda_runtime.h>
#include <cuda_fp16.h>
#include <cstdint>

// Problem constants
#define BDIM  4096
#define TDIM  32
#define KDIM  16
#define DDIM  512
#define HDIM  1024   // = 2*D
#define H2DIM 2048   // = 2*H

// NOTE: harness PTX target is compute_103 (no 'a') -> tcgen05/TMEM rejected.
// Legacy mma.sync HMMA is the tensor path. All GEMMs single-pass fp16.
// Mainloop = R10 optimum (256 thr, 2 CTAs/SM, 128 regs, BK=32, 32x64 warp
// tile, 3-stage/wait-1) + R16 split-N grids. R17 single delta: drop the
// redundant trailing __syncthreads per k-tile (leading wait+sync barrier
// already orders buffer reuse with NSTG=3).

// ---------------------------------------------------------------------------
// Scratch (device globals: allocation-free rule)
// ---------------------------------------------------------------------------
__device__ float E1_buf[BDIM * HDIM];
__device__ float E2_buf[BDIM * H2DIM];
__device__ float e_buf[BDIM * TDIM];
__device__ float part_buf[16 * BDIM * TDIM / 2 * 2];   // 1M floats

__device__ __half Xh_buf[BDIM * TDIM * DDIM];
__device__ __half Gh_buf[BDIM * KDIM * DDIM];
__device__ __half W1h_buf[2 * DDIM * HDIM];   // full W1 (1024 x 1024)
__device__ __half M1h_buf[2 * DDIM * H2DIM];  // full M1 (1024 x 2048)
__device__ __half ghh_buf[BDIM * DDIM];
__device__ __half xhh_buf[BDIM * DDIM];

// ---------------------------------------------------------------------------
// PTX helpers
// ---------------------------------------------------------------------------
__device__ __forceinline__ void cp16(uint32_t dst, const void* src) {
    asm volatile("cp.async.cg.shared.global [%0], [%1], 16;\n"
                 :: "r"(dst), "l"(src) : "memory");
}
__device__ __forceinline__ void cp_commit() {
    asm volatile("cp.async.commit_group;\n" ::: "memory");
}
__device__ __forceinline__ void cp_wait1() {
    asm volatile("cp.async.wait_group 1;\n" ::: "memory");
}
__device__ __forceinline__ void ldsm_x4(unsigned& d0, unsigned& d1, unsigned& d2,
                                        unsigned& d3, uint32_t addr) {
    asm volatile("ldmatrix.sync.aligned.m8n8.x4.shared.b16 {%0,%1,%2,%3}, [%4];\n"
                 : "=r"(d0), "=r"(d1), "=r"(d2), "=r"(d3) : "r"(addr));
}
__device__ __forceinline__ void ldsm_x4_t(unsigned& d0, unsigned& d1, unsigned& d2,
                                          unsigned& d3, uint32_t addr) {
    asm volatile("ldmatrix.sync.aligned.m8n8.x4.trans.shared.b16 {%0,%1,%2,%3}, [%4];\n"
                 : "=r"(d0), "=r"(d1), "=r"(d2), "=r"(d3) : "r"(addr));
}
__device__ __forceinline__ void mma16816(float c[4], const unsigned a[4], const unsigned b[2]) {
    asm volatile(
        "mma.sync.aligned.m16n8k16.row.col.f32.f16.f16.f32 "
        "{%0,%1,%2,%3}, {%4,%5,%6,%7}, {%8,%9}, {%0,%1,%2,%3};\n"
        : "+f"(c[0]), "+f"(c[1]), "+f"(c[2]), "+f"(c[3])
        : "r"(a[0]), "r"(a[1]), "r"(a[2]), "r"(a[3]), "r"(b[0]), "r"(b[1]));
}

// ---------------------------------------------------------------------------
// convert-only: hi = fp16(x)
// ---------------------------------------------------------------------------
__global__ void conv_fp16_kernel(const float* __restrict__ src,
                                 __half* __restrict__ hi)
{
    int i = blockIdx.x * blockDim.x + threadIdx.x;
    float4 v = ((const float4*)src)[i];
    __half h[4];
    h[0] = __float2half_rn(v.x); h[1] = __float2half_rn(v.y);
    h[2] = __float2half_rn(v.z); h[3] = __float2half_rn(v.w);
    ((uint2*)hi)[i] = *(uint2*)h;
}

// ---------------------------------------------------------------------------
// fused: G -> Gh (fp16) AND ghh = fp16(mean_k G)   (single read of G)
// ---------------------------------------------------------------------------
__global__ void gconv_gmean_kernel(const float* __restrict__ G,
                                   __half* __restrict__ Gh,
                                   __half* __restrict__ ghh)
{
    int idx = blockIdx.x * blockDim.x + threadIdx.x;   // over B * (D/4)
    int b  = idx >> 7;
    int ch = idx & 127;
    const float4* gp = (const float4*)(G + (size_t)b * KDIM * DDIM + ch * 4);
    float4 acc = make_float4(0.f, 0.f, 0.f, 0.f);
#pragma unroll
    for (int k = 0; k < KDIM; k++) {
        float4 v = gp[k * (DDIM / 4)];
        __half h[4];
        h[0] = __float2half_rn(v.x); h[1] = __float2half_rn(v.y);
        h[2] = __float2half_rn(v.z); h[3] = __float2half_rn(v.w);
        ((uint2*)Gh)[((size_t)b * KDIM * DDIM + (size_t)k * DDIM) / 4 + ch] = *(uint2*)h;
        acc.x += v.x; acc.y += v.y; acc.z += v.z; acc.w += v.w;
    }
    const float inv = 1.0f / KDIM;
    __half m[4];
    m[0] = __float2half_rn(acc.x * inv); m[1] = __float2half_rn(acc.y * inv);
    m[2] = __float2half_rn(acc.z * inv); m[3] = __float2half_rn(acc.w * inv);
    ((uint2*)ghh)[idx] = *(uint2*)m;
}

// ---------------------------------------------------------------------------
// fp16 tensor-core GEMM, one 128x128 output tile per CTA.
// grid = (N/128, M/128); x (n-tile) fastest -> CTAs sharing rb are adjacent
// and share the A tile through L2.
// REDUCE=true : partial[row] = sum_{n in tile} relu(acc + Eb[row>>SHIFT, n])*wvec[n]
//               written to out[cb_tile * M + row]  (part buffer)
// REDUCE=false: out[row,col] = acc + bias[col]
// ---------------------------------------------------------------------------
constexpr int ASZ = 128 * 40 * 2;     // one A stage (bytes)
constexpr int BSZ = 32 * 136 * 2;     // one B stage (bytes)
constexpr int NSTG = 3;
constexpr int SMEM_BYTES = NSTG * (ASZ + BSZ) + 128 * 2 * 4;
constexpr int NKT = DDIM / 32;        // 16 k-tiles

template <int RPB_SHIFT, bool REDUCE>
__global__ void __launch_bounds__(256, 2) mma_gemm(
    const __half* __restrict__ Ah,
    const __half* __restrict__ Bh,
    const float* __restrict__ EbOrBias,
    const float* __restrict__ wvec,
    float* __restrict__ out,
    int N)
{
    extern __shared__ __align__(16) char smraw[];
    float* red = (float*)(smraw + NSTG * (ASZ + BSZ));   // [128][2]

    const int tid  = threadIdx.x;
    const int lane = tid & 31;
    const int wid  = tid >> 5;
    const int warp_m = wid & 3;       // 4 warps in M
    const int warp_n = wid >> 2;      // 2 warps in N
    const int lq = lane >> 2, lr = lane & 3;
    const int rb = (int)blockIdx.y << 7;
    const int cb = (int)blockIdx.x << 7;

    const uint32_t uS = (uint32_t)__cvta_generic_to_shared(smraw);
    const uint32_t uA = uS;
    const uint32_t uB = uS + NSTG * ASZ;

    // staging chunk coords (A: 2 chunks, B: 2 chunks per thread per tile)
    int am[2], ak[2], bk[2], bn[2];
#pragma unroll
    for (int c = 0; c < 2; c++) {
        int cid = tid + c * 256;
        am[c] = cid >> 2;  ak[c] = (cid & 3) << 3;
        bk[c] = cid >> 4;  bn[c] = (cid & 15) << 3;
    }

    // ldmatrix per-lane address components
    const uint32_t a_frag_off =
        (uint32_t)(((warp_m * 32 + (lane & 15)) * 40 + ((lane & 16) >> 1)) * 2);
    const uint32_t b_frag_off =
        (uint32_t)(((lane & 15) * 136 + warp_n * 64 + ((lane & 16) >> 1)) * 2);

    float c[2][8][4] = {};

    auto stage = [&](int buf, int kt) {
        const int koff = kt << 5;
        const uint32_t adst0 = uA + (uint32_t)(buf * ASZ);
        const uint32_t bdst0 = uB + (uint32_t)(buf * BSZ);
#pragma unroll
        for (int cc = 0; cc < 2; cc++) {
            cp16(adst0 + (uint32_t)((am[cc] * 40 + ak[cc]) * 2),
                 Ah + (size_t)(rb + am[cc]) * DDIM + koff + ak[cc]);
            cp16(bdst0 + (uint32_t)((bk[cc] * 136 + bn[cc]) * 2),
                 Bh + (size_t)(koff + bk[cc]) * N + cb + bn[cc]);
        }
    };

    stage(0, 0);
    cp_commit();

    for (int kt = 0; kt < NKT; kt++) {
        if (kt < NKT - 1) stage((kt + 1) % NSTG, kt + 1);
        cp_commit();
        cp_wait1();
        __syncthreads();   // single barrier per k-tile: orders tile-kt data
                           // visibility AND (via the kt+1 instance) all
                           // compute(kt) before buffer kt%3 is re-staged at kt+2

        const int buf = kt % NSTG;
        const uint32_t Ahb = uA + (uint32_t)(buf * ASZ) + a_frag_off;
        const uint32_t Bhb = uB + (uint32_t)(buf * BSZ) + b_frag_off;

#pragma unroll
        for (int kk = 0; kk < 32; kk += 16) {
            unsigned ah[2][4], bh[8][2];
#pragma unroll
            for (int mi = 0; mi < 2; mi++)
                ldsm_x4(ah[mi][0], ah[mi][1], ah[mi][2], ah[mi][3],
                        Ahb + (uint32_t)((mi * 16 * 40 + kk) * 2));
#pragma unroll
            for (int gg = 0; gg < 4; gg++)
                ldsm_x4_t(bh[2*gg][0], bh[2*gg][1], bh[2*gg+1][0], bh[2*gg+1][1],
                          Bhb + (uint32_t)((kk * 136 + gg * 16) * 2));
#pragma unroll
            for (int mi = 0; mi < 2; mi++)
#pragma unroll
                for (int ni = 0; ni < 8; ni++)
                    mma16816(c[mi][ni], ah[mi], bh[ni]);
        }
    }

    if (REDUCE) {
        // fused epilogue: relu(acc + Eb) . wvec -> partial row sums
        float rs[2][2] = {{0.f, 0.f}, {0.f, 0.f}};
#pragma unroll
        for (int mi = 0; mi < 2; mi++) {
            int row0 = rb + warp_m * 32 + mi * 16 + lq;
            int row1 = row0 + 8;
            const float* Eb0 = EbOrBias + (size_t)(row0 >> RPB_SHIFT) * N;
            const float* Eb1 = EbOrBias + (size_t)(row1 >> RPB_SHIFT) * N;
#pragma unroll
            for (int ni = 0; ni < 8; ni++) {
                int col = cb + warp_n * 64 + ni * 8 + lr * 2;
                float2 e0 = *(const float2*)&Eb0[col];
                float2 e1 = *(const float2*)&Eb1[col];
                float2 wv = *(const float2*)&wvec[col];
                rs[mi][0] += fmaxf(c[mi][ni][0] + e0.x, 0.f) * wv.x
                           + fmaxf(c[mi][ni][1] + e0.y, 0.f) * wv.y;
                rs[mi][1] += fmaxf(c[mi][ni][2] + e1.x, 0.f) * wv.x
                           + fmaxf(c[mi][ni][3] + e1.y, 0.f) * wv.y;
            }
        }
        // reduce across the 4 lanes sharing each row, then across warp_n
#pragma unroll
        for (int mi = 0; mi < 2; mi++)
#pragma unroll
            for (int h = 0; h < 2; h++) {
                float s = rs[mi][h];
                s += __shfl_xor_sync(0xffffffffu, s, 1);
                s += __shfl_xor_sync(0xffffffffu, s, 2);
                if (lr == 0)
                    red[(warp_m * 32 + mi * 16 + h * 8 + lq) * 2 + warp_n] = s;
            }
        __syncthreads();
        if (tid < 128) {
            size_t M = (size_t)gridDim.y << 7;
            out[(size_t)blockIdx.x * M + rb + tid] =
                red[tid * 2 + 0] + red[tid * 2 + 1];
        }
    } else {
        // plain store epilogue: C = acc + bias
#pragma unroll
        for (int mi = 0; mi < 2; mi++) {
            int row0 = rb + warp_m * 32 + mi * 16 + lq;
            int row1 = row0 + 8;
#pragma unroll
            for (int ni = 0; ni < 8; ni++) {
                int col = cb + warp_n * 64 + ni * 8 + lr * 2;
                float2 bv = *(const float2*)&EbOrBias[col];
                float2 o0, o1;
                o0.x = c[mi][ni][0] + bv.x; o0.y = c[mi][ni][1] + bv.y;
                o1.x = c[mi][ni][2] + bv.x; o1.y = c[mi][ni][3] + bv.y;
                *(float2*)&out[(size_t)row0 * N + col] = o0;
                *(float2*)&out[(size_t)row1 * N + col] = o1;
            }
        }
    }
}

// ---------------------------------------------------------------------------
// final reduction: out[i] = sum_nt part[nt*M + i] (+ *addsc), float4 per thread
// ---------------------------------------------------------------------------
template <int NT>
__global__ void reduce_final_kernel(const float* __restrict__ part,
                                    float* __restrict__ out,
                                    const float* __restrict__ addsc,
                                    int M)
{
    int i = blockIdx.x * blockDim.x + threadIdx.x;    // over M/4
    const float4* p = (const float4*)part;
    float4 s = p[i];
#pragma unroll
    for (int nt = 1; nt < NT; nt++) {
        float4 v = p[(size_t)nt * (M >> 2) + i];
        s.x += v.x; s.y += v.y; s.z += v.z; s.w += v.w;
    }
    if (addsc) {
        float a = *addsc;
        s.x += a; s.y += a; s.z += a; s.w += a;
    }
    ((float4*)out)[i] = s;
}

// ---------------------------------------------------------------------------
// K4: per-b softmax over T=32 then x_hat = sum_t alpha_t * Xh[b,t,:] -> fp16
// ---------------------------------------------------------------------------
__global__ void softmax_xhat_kernel(const float* __restrict__ e,
                                    const __half* __restrict__ Xh,
                                    __half* __restrict__ xh)
{
    int b = blockIdx.x;
    __shared__ float alpha[TDIM];
    int tid = threadIdx.x;   // 128 threads
    if (tid < 32) {
        float v = e[b * TDIM + tid];
        float m = v;
#pragma unroll
        for (int off = 16; off >= 1; off >>= 1)
            m = fmaxf(m, __shfl_xor_sync(0xffffffffu, m, off));
        float ex = __expf(v - m);
        float s = ex;
#pragma unroll
        for (int off = 16; off >= 1; off >>= 1)
            s += __shfl_xor_sync(0xffffffffu, s, off);
        alpha[tid] = ex / s;
    }
    __syncthreads();
    const __half* Xb = Xh + (size_t)b * TDIM * DDIM + tid * 4;
    float s0 = 0.f, s1 = 0.f, s2 = 0.f, s3 = 0.f;
#pragma unroll
    for (int t = 0; t < TDIM; t++) {
        uint2 raw = *(const uint2*)&Xb[t * DDIM];
        __half2 p0 = *(__half2*)&raw.x;
        __half2 p1 = *(__half2*)&raw.y;
        float a = alpha[t];
        s0 += a * __low2float(p0);  s1 += a * __high2float(p0);
        s2 += a * __low2float(p1);  s3 += a * __high2float(p1);
    }
    __half hh[4];
    hh[0] = __float2half_rn(s0); hh[1] = __float2half_rn(s1);
    hh[2] = __float2half_rn(s2); hh[3] = __float2half_rn(s3);
    ((uint2*)xh)[((size_t)b * DDIM + tid * 4) >> 2] = *(uint2*)hh;
}

// ---------------------------------------------------------------------------
extern "C" void kernel_launch(void* const* d_in, const int* in_sizes, int n_in,
                              void* d_out, int out_size)
{
    const float* X  = (const float*)d_in[0];
    const float* G  = (const float*)d_in[1];
    const float* W1 = (const float*)d_in[2];
    const float* b1 = (const float*)d_in[3];
    const float* w2 = (const float*)d_in[4];
    // d_in[5] = b2: softmax shift-invariant, unused
    const float* M1 = (const float*)d_in[6];
    const float* c1 = (const float*)d_in[7];
    const float* m2 = (const float*)d_in[8];
    const float* c2 = (const float*)d_in[9];
    float* out = (float*)d_out;

    float *E1, *E2, *ebuf, *part;
    cudaGetSymbolAddress((void**)&E1,   E1_buf);
    cudaGetSymbolAddress((void**)&E2,   E2_buf);
    cudaGetSymbolAddress((void**)&ebuf, e_buf);
    cudaGetSymbolAddress((void**)&part, part_buf);

    __half *Xh, *Gh, *W1h, *M1h, *ghh, *xhh;
    cudaGetSymbolAddress((void**)&Xh,  Xh_buf);
    cudaGetSymbolAddress((void**)&Gh,  Gh_buf);
    cudaGetSymbolAddress((void**)&W1h, W1h_buf);
    cudaGetSymbolAddress((void**)&M1h, M1h_buf);
    cudaGetSymbolAddress((void**)&ghh, ghh_buf);
    cudaGetSymbolAddress((void**)&xhh, xhh_buf);

    cudaFuncSetAttribute((const void*)mma_gemm<5, true>,
                         cudaFuncAttributeMaxDynamicSharedMemorySize, SMEM_BYTES);
    cudaFuncSetAttribute((const void*)mma_gemm<4, true>,
                         cudaFuncAttributeMaxDynamicSharedMemorySize, SMEM_BYTES);
    cudaFuncSetAttribute((const void*)mma_gemm<0, false>,
                         cudaFuncAttributeMaxDynamicSharedMemorySize, SMEM_BYTES);

    // [0] convert X -> fp16
    conv_fp16_kernel<<<(BDIM * TDIM * DDIM / 4) / 256, 256>>>(X, Xh);
    // [1] convert W1 -> fp16
    conv_fp16_kernel<<<(2 * DDIM * HDIM / 4) / 256, 256>>>(W1, W1h);
    // [2] fused: G -> Gh, ghh = mean_k G (single read of G)
    gconv_gmean_kernel<<<(BDIM * DDIM / 4) / 256, 256>>>(G, Gh, ghh);
    // [3] K2: E1 = g_hat @ W1[:512] + b1   (4096 x 1024)
    mma_gemm<0, false><<<dim3(HDIM / 128, BDIM / 128), 256, SMEM_BYTES>>>(
        ghh, W1h, b1, nullptr, E1, HDIM);
    // [4] convert M1 -> fp16
    conv_fp16_kernel<<<(2 * DDIM * H2DIM / 4) / 256, 256>>>(M1, M1h);
    // [5] K3: partial e sums over each 128-col slice   (M = 131072, 8 n-tiles)
    mma_gemm<5, true><<<dim3(HDIM / 128, (BDIM * TDIM) / 128), 256, SMEM_BYTES>>>(
        Xh, W1h + (size_t)DDIM * HDIM, E1, w2, part, HDIM);
    // [6] e = sum of 8 partials
    reduce_final_kernel<8><<<(BDIM * TDIM / 4) / 256, 256>>>(
        part, ebuf, nullptr, BDIM * TDIM);
    // [7] softmax over T + x_hat -> fp16
    softmax_xhat_kernel<<<BDIM, 128>>>(ebuf, Xh, xhh);
    // [8] K5: E2 = x_hat @ M1[:512] + c1   (4096 x 2048)
    mma_gemm<0, false><<<dim3(H2DIM / 128, BDIM / 128), 256, SMEM_BYTES>>>(
        xhh, M1h, c1, nullptr, E2, H2DIM);
    // [9] K6: partial logit sums   (M = 65536, 16 n-tiles)
    mma_gemm<4, true><<<dim3(H2DIM / 128, (BDIM * KDIM) / 128), 256, SMEM_BYTES>>>(
        Gh, M1h + (size_t)DDIM * H2DIM, E2, m2, part, H2DIM);
    // [10] logits = sum of 16 partials + c2
    reduce_final_kernel<16><<<(BDIM * KDIM / 4) / 256, 256>>>(
        part, out, c2, BDIM * KDIM);
}